// round 13
// baseline (speedup 1.0000x reference)
#include <cuda_runtime.h>
#include <cuda_bf16.h>
#include <cstdint>

#define NPROTO 64
#define PDIM   512
#define NFEAT  200000
#define EPSN   1e-8f
#define NACC   148                       // persistent CTAs (== #partial slices)
#define CHUNK  32                        // rows per staged chunk
#define NCHUNK (NFEAT / CHUNK)           // 6250, exact (no tail)

// ---------------- device scratch (static; no allocation) ----------------
// B fragments, coalesced: g_B[(nblk*32+ks)*32 + lane], lane = rg*4+q holds
// { bf16x2(Pn[16ks+2q..]), bf16x2(Pn[16ks+8+2q..]) } for proto n = nblk*8+rg.
__device__ uint2 g_B[8 * 32 * 32];
__device__ float g_Partial[NACC * NPROTO * PDIM];   // per-CTA segment sums (~19.4 MB)
__device__ int   g_Cnt[NPROTO];

__device__ __forceinline__ uint32_t smem_u32(const void* p) {
    uint32_t a;
    asm("{ .reg .u64 t; cvta.to.shared.u64 t, %1; cvt.u32.u64 %0, t; }" : "=r"(a) : "l"(p));
    return a;
}

// ---------------- kernel 1: normalize prototypes -> coalesced bf16 frags ----------------
__global__ void prep_kernel(const float* __restrict__ P) {
    int k = blockIdx.x;          // 64 blocks (one proto each)
    int t = threadIdx.x;         // 128 threads
    const float* row = P + k * PDIM;
    if (t == 0) g_Cnt[k] = 0;    // re-zeroed every replay before fused kernel

    float ss = 0.f;
    #pragma unroll
    for (int i = 0; i < 4; ++i) { float v = row[t + 128 * i]; ss += v * v; }
    __shared__ float red[4];
    #pragma unroll
    for (int o = 16; o > 0; o >>= 1) ss += __shfl_xor_sync(0xffffffffu, ss, o);
    if ((t & 31) == 0) red[t >> 5] = ss;
    __syncthreads();
    float norm = sqrtf(red[0] + red[1] + red[2] + red[3]);
    float inv = 1.f / fmaxf(norm, EPSN);

    int ks = t >> 2, q = t & 3;                    // 32 ksteps x 4 q
    int i0 = ks * 8 + q;                           // float2 index in row
    float2 fa = make_float2(row[2 * i0] * inv,       row[2 * i0 + 1] * inv);
    float2 fb = make_float2(row[2 * (i0 + 4)] * inv, row[2 * (i0 + 4) + 1] * inv);
    __nv_bfloat162 ha = __float22bfloat162_rn(fa);
    __nv_bfloat162 hb = __float22bfloat162_rn(fb);
    uint2 u;
    u.x = *reinterpret_cast<uint32_t*>(&ha);
    u.y = *reinterpret_cast<uint32_t*>(&hb);
    g_B[((k >> 3) * 32 + ks) * 32 + (k & 7) * 4 + q] = u;
}

// ---------------- kernel 2: FUSED, A-fragment-deduped MMA split ----------------
// 148 persistent CTAs x 512 threads, 2 __syncthreads per chunk.
// Warp w: row block rbw=w>>3 (16 rows), proto half np=w&1 (32 protos = 4 nblk),
// k-quarter kh=(w>>1)&3 (8 ksteps). One ldmatrix feeds 4 mma (A reuse x4).
// fp32 partials (4 kh copies) reduced deterministically + argmax in next phase A.
// Per chunk k: [A] stage(k)->buf[k&1] + reduce/argmax(k-1); S1;
//              [B] prefetch(k+1) + mma-partials(k) || accumulate(k-1); S2.
__global__ __launch_bounds__(512) void fused_kernel(const float* __restrict__ F) {
    extern __shared__ float acc[];                        // 64*512 f32 = 128 KB
    char*  s_A    = (char*)(acc + NPROTO * PDIM);         // 2 bufs x 32 rows x 1024B
    float* s_part = (float*)(s_A + 2 * CHUNK * 1024);     // [2rb][2np][4kh][16][32] = 32 KB
    unsigned char* s_asg = (unsigned char*)(s_part + 8192);   // [2][32], 8B-aligned

    int t = threadIdx.x;
    #pragma unroll
    for (int i = 0; i < NPROTO; ++i) acc[i * PDIM + t] = 0.f;

    int w = t >> 5, lane = t & 31;
    int np  = w & 1;                      // proto half: protos np*32..+32
    int kh  = (w >> 1) & 3;               // k-quarter: ksteps kh*8..+8
    int rbw = w >> 3;                     // row block: rows rbw*16..+16
    int q = lane & 3, rg = lane >> 2;
    int rowB = rbw * 16 + (lane & 15);    // ldmatrix row
    int halfSel = lane >> 4;              // 16B half selector
    uint32_t sA0 = smem_u32(s_A);

    // resident B fragments: 8 ks x 4 nblk (64 regs)
    uint2 Bf[8][4];
    #pragma unroll
    for (int i = 0; i < 8; ++i)
        #pragma unroll
        for (int nb = 0; nb < 4; ++nb)
            Bf[i][nb] = g_B[((np * 4 + nb) * 32 + kh * 8 + i) * 32 + lane];

    // accumulate addressing: thread t -> rows half rh, column pair cp
    int rh = t >> 8;                      // 0/1 -> rows rh*16..rh*16+15
    int cp = t & 255;                     // float2 column pair (cols 2cp, 2cp+1)
    int i16c = cp >> 2, inoffc = (cp & 3) * 4;
    float2* accp = reinterpret_cast<float2*>(acc);

    const float4* F4 = reinterpret_cast<const float4*>(F);
    int n = (NCHUNK - blockIdx.x + NACC - 1) / NACC;      // 42 or 43 chunks
    int cnt = 0;

    // prologue: prefetch + convert chunk 0 (8 x LDG.128 per thread, coalesced)
    uint2 u[8];
    {
        size_t cb = (size_t)blockIdx.x * (CHUNK * 128);
        #pragma unroll
        for (int j = 0; j < 8; ++j) {
            float4 v = F4[cb + j * 512 + t];
            __nv_bfloat162 h0 = __float22bfloat162_rn(make_float2(v.x, v.y));
            __nv_bfloat162 h1 = __float22bfloat162_rn(make_float2(v.z, v.w));
            u[j].x = *reinterpret_cast<uint32_t*>(&h0);
            u[j].y = *reinterpret_cast<uint32_t*>(&h1);
        }
    }
    __syncthreads();

    for (int k = 0; k < n; ++k) {
        // ======== phase A: stage(k) + reduce/argmax(k-1) ========
        char* dst = s_A + (k & 1) * (CHUNK * 1024);
        #pragma unroll
        for (int j = 0; j < 8; ++j) {
            int idx = j * 512 + t;                // 0..4095 float4s
            int row = idx >> 7;
            int c4  = idx & 127;
            int i16 = c4 >> 1;
            int sw  = (i16 & ~7) | ((i16 ^ row) & 7);
            *reinterpret_cast<uint2*>(dst + row * 1024 + sw * 16 + (c4 & 1) * 8) = u[j];
        }
        if (k > 0) {
            // reduce 4 kh partials + argmax; warp w handles rows w and w+16
            #pragma unroll
            for (int rr = 0; rr < 2; ++rr) {
                int r  = w + rr * 16;
                int rbr = r >> 4, ri = r & 15;
                int csw = lane ^ ((ri & 3) << 3);
                float s0 = 0.f, s1 = 0.f;
                #pragma unroll
                for (int h = 0; h < 4; ++h) {
                    s0 += s_part[(((rbr * 2 + 0) * 4 + h) * 16 + ri) * 32 + csw];
                    s1 += s_part[(((rbr * 2 + 1) * 4 + h) * 16 + ri) * 32 + csw];
                }
                float bv = s0; int bi = lane;
                if (s1 > bv) { bv = s1; bi = lane + 32; }
                #pragma unroll
                for (int off = 1; off < 32; off <<= 1) {
                    float ov = __shfl_xor_sync(0xffffffffu, bv, off);
                    int   oi = __shfl_xor_sync(0xffffffffu, bi, off);
                    if (ov > bv || (ov == bv && oi < bi)) { bv = ov; bi = oi; }
                }
                if (lane == 0) s_asg[((k - 1) & 1) * 32 + r] = (unsigned char)bi;
            }
        }
        __syncthreads();   // S1

        // ======== phase B: prefetch(k+1) + mma(k) || accumulate(k-1) ========
        if (k + 1 < n) {
            size_t cb = (size_t)(blockIdx.x + (k + 1) * NACC) * (CHUNK * 128);
            #pragma unroll
            for (int j = 0; j < 8; ++j) {
                float4 v = F4[cb + j * 512 + t];
                __nv_bfloat162 h0 = __float22bfloat162_rn(make_float2(v.x, v.y));
                __nv_bfloat162 h1 = __float22bfloat162_rn(make_float2(v.z, v.w));
                u[j].x = *reinterpret_cast<uint32_t*>(&h0);
                u[j].y = *reinterpret_cast<uint32_t*>(&h1);
            }
        }

        // ---- mma partials: 16 rows x 32 protos over 8 ksteps ----
        {
            uint32_t base = sA0 + (uint32_t)(k & 1) * (CHUNK * 1024);
            float d[4][4];
            #pragma unroll
            for (int nb = 0; nb < 4; ++nb)
                d[nb][0] = d[nb][1] = d[nb][2] = d[nb][3] = 0.f;
            #pragma unroll
            for (int i = 0; i < 8; ++i) {
                int i16 = (kh * 8 + i) * 2 + halfSel;
                int sw = (i16 & ~7) | ((i16 ^ rowB) & 7);
                uint32_t addr = base + rowB * 1024 + sw * 16;
                uint32_t a0, a1, a2, a3;
                asm volatile("ldmatrix.sync.aligned.m8n8.x4.shared.b16 {%0,%1,%2,%3}, [%4];"
                             : "=r"(a0), "=r"(a1), "=r"(a2), "=r"(a3) : "r"(addr));
                #pragma unroll
                for (int nb = 0; nb < 4; ++nb) {
                    asm volatile(
                        "mma.sync.aligned.m16n8k16.row.col.f32.bf16.bf16.f32 "
                        "{%0,%1,%2,%3}, {%4,%5,%6,%7}, {%8,%9}, {%0,%1,%2,%3};"
                        : "+f"(d[nb][0]), "+f"(d[nb][1]), "+f"(d[nb][2]), "+f"(d[nb][3])
                        : "r"(a0), "r"(a1), "r"(a2), "r"(a3),
                          "r"(Bf[i][nb].x), "r"(Bf[i][nb].y));
                }
            }
            // store partials: lane holds (row rg+(j>>1)*8, p32 = nb*8+2q+(j&1))
            int regionbase = ((rbw * 2 + np) * 4 + kh) * 16;
            #pragma unroll
            for (int nb = 0; nb < 4; ++nb) {
                #pragma unroll
                for (int j = 0; j < 4; ++j) {
                    int row = rg + (j >> 1) * 8;
                    int p32 = nb * 8 + 2 * q + (j & 1);
                    s_part[(regionbase + row) * 32 + (p32 ^ ((row & 3) << 3))] = d[nb][j];
                }
            }
        }

        // ---- accumulate chunk k-1 (same phase: overlaps mma across warps) ----
        if (k > 0) {
            int pb = (k - 1) & 1;
            const char* src = s_A + pb * (CHUNK * 1024);
            unsigned long long w0 = *reinterpret_cast<const unsigned long long*>(s_asg + pb * 32 + rh * 16);
            unsigned long long w1 = *reinterpret_cast<const unsigned long long*>(s_asg + pb * 32 + rh * 16 + 8);
            #pragma unroll
            for (int j = 0; j < 16; ++j) {
                int r = rh * 16 + j;
                int sw = (i16c & ~7) | ((i16c ^ r) & 7);
                uint32_t hv = *reinterpret_cast<const uint32_t*>(src + r * 1024 + sw * 16 + inoffc);
                __nv_bfloat162 h = *reinterpret_cast<__nv_bfloat162*>(&hv);
                float2 f = __bfloat1622float2(h);
                int a = (int)(((j < 8 ? w0 : w1) >> ((j & 7) * 8)) & 255ull);
                float2 cur = accp[a * (PDIM / 2) + cp];
                cur.x += f.x; cur.y += f.y;
                accp[a * (PDIM / 2) + cp] = cur;
            }
            if (t < NPROTO) {
                #pragma unroll
                for (int jj = 0; jj < 4; ++jj) {
                    unsigned long long x = *reinterpret_cast<const unsigned long long*>(s_asg + pb * 32 + jj * 8);
                    #pragma unroll
                    for (int b = 0; b < 8; ++b)
                        cnt += (int)(((x >> (8 * b)) & 255ull) == (unsigned long long)t);
                }
            }
        }
        __syncthreads();   // S2
    }

    // ======== epilogue: reduce/argmax + accumulate for chunk n-1 ========
    {
        int kk = n - 1;
        #pragma unroll
        for (int rr = 0; rr < 2; ++rr) {
            int r  = w + rr * 16;
            int rbr = r >> 4, ri = r & 15;
            int csw = lane ^ ((ri & 3) << 3);
            float s0 = 0.f, s1 = 0.f;
            #pragma unroll
            for (int h = 0; h < 4; ++h) {
                s0 += s_part[(((rbr * 2 + 0) * 4 + h) * 16 + ri) * 32 + csw];
                s1 += s_part[(((rbr * 2 + 1) * 4 + h) * 16 + ri) * 32 + csw];
            }
            float bv = s0; int bi = lane;
            if (s1 > bv) { bv = s1; bi = lane + 32; }
            #pragma unroll
            for (int off = 1; off < 32; off <<= 1) {
                float ov = __shfl_xor_sync(0xffffffffu, bv, off);
                int   oi = __shfl_xor_sync(0xffffffffu, bi, off);
                if (ov > bv || (ov == bv && oi < bi)) { bv = ov; bi = oi; }
            }
            if (lane == 0) s_asg[(kk & 1) * 32 + r] = (unsigned char)bi;
        }
        __syncthreads();
        int pb = kk & 1;
        const char* src = s_A + pb * (CHUNK * 1024);
        unsigned long long w0 = *reinterpret_cast<const unsigned long long*>(s_asg + pb * 32 + rh * 16);
        unsigned long long w1 = *reinterpret_cast<const unsigned long long*>(s_asg + pb * 32 + rh * 16 + 8);
        #pragma unroll
        for (int j = 0; j < 16; ++j) {
            int r = rh * 16 + j;
            int sw = (i16c & ~7) | ((i16c ^ r) & 7);
            uint32_t hv = *reinterpret_cast<const uint32_t*>(src + r * 1024 + sw * 16 + inoffc);
            __nv_bfloat162 h = *reinterpret_cast<__nv_bfloat162*>(&hv);
            float2 f = __bfloat1622float2(h);
            int a = (int)(((j < 8 ? w0 : w1) >> ((j & 7) * 8)) & 255ull);
            float2 cur = accp[a * (PDIM / 2) + cp];
            cur.x += f.x; cur.y += f.y;
            accp[a * (PDIM / 2) + cp] = cur;
        }
        if (t < NPROTO) {
            #pragma unroll
            for (int jj = 0; jj < 4; ++jj) {
                unsigned long long x = *reinterpret_cast<const unsigned long long*>(s_asg + pb * 32 + jj * 8);
                #pragma unroll
                for (int b = 0; b < 8; ++b)
                    cnt += (int)(((x >> (8 * b)) & 255ull) == (unsigned long long)t);
            }
        }
    }
    __syncthreads();

    // deterministic flush of this CTA's partial slice
    float* part = g_Partial + (size_t)blockIdx.x * (NPROTO * PDIM);
    #pragma unroll 4
    for (int k = 0; k < NPROTO; ++k) part[k * PDIM + t] = acc[k * PDIM + t];
    if (t < NPROTO) atomicAdd(&g_Cnt[t], cnt);   // int atomics: deterministic
}

// ---------------- kernel 3: reduce partials + EMA update ----------------
__global__ void finalize_kernel(const float* __restrict__ P, float* __restrict__ out) {
    int k = blockIdx.x >> 3;                          // 64 protos x 8 col-groups
    int t = ((blockIdx.x & 7) << 6) + threadIdx.x;    // 64 threads -> column
    float s = 0.f;
    #pragma unroll 8
    for (int b = 0; b < NACC; ++b)
        s += g_Partial[(size_t)b * (NPROTO * PDIM) + k * PDIM + t];
    int c = g_Cnt[k];
    float p = P[k * PDIM + t];
    float mean = s / fmaxf((float)c, 1.f);
    out[k * PDIM + t] = (c > 0) ? (0.9f * p + 0.1f * mean) : p;
}

// ---------------- launch ----------------
extern "C" void kernel_launch(void* const* d_in, const int* in_sizes, int n_in,
                              void* d_out, int out_size) {
    const float* F = (const float*)d_in[0];
    const float* P = (const float*)d_in[1];
    if (in_sizes[0] == NPROTO * PDIM) {     // robust to input order
        F = (const float*)d_in[1];
        P = (const float*)d_in[0];
    }

    prep_kernel<<<NPROTO, 128>>>(P);

    int smem = NPROTO * PDIM * (int)sizeof(float)   // 128 KB accumulator
             + 2 * CHUNK * 1024                     // 64 KB double-buffered staging
             + 8192 * (int)sizeof(float)            // 32 KB partials [2][2][4][16][32]
             + 64;                                  // s_asg[2][32]
    cudaFuncSetAttribute(fused_kernel, cudaFuncAttributeMaxDynamicSharedMemorySize, smem);
    fused_kernel<<<NACC, 512, smem>>>(F);

    finalize_kernel<<<NPROTO * 8, 64>>>(P, (float*)d_out);
}

// round 14
// speedup vs baseline: 1.1224x; 1.1224x over previous
#include <cuda_runtime.h>
#include <cuda_bf16.h>
#include <cstdint>

#define NPROTO 64
#define PDIM   512
#define NFEAT  200000
#define EPSN   1e-8f
#define NACC   148                       // persistent CTAs (== #partial slices)
#define CHUNK  32                        // rows per staged chunk
#define NCHUNK (NFEAT / CHUNK)           // 6250, exact (no tail)

// ---------------- device scratch (static; no allocation) ----------------
// B fragments, coalesced: g_B[(nblk*32+ks)*32 + lane], lane = rg*4+q holds
// { bf16x2(Pn[16ks+2q..]), bf16x2(Pn[16ks+8+2q..]) } for proto n = nblk*8+rg.
__device__ uint2 g_B[8 * 32 * 32];
__device__ float g_Partial[NACC * NPROTO * PDIM];   // per-CTA segment sums (~19.4 MB)
__device__ int   g_Cnt[NPROTO];

__device__ __forceinline__ uint32_t smem_u32(const void* p) {
    uint32_t a;
    asm("{ .reg .u64 t; cvta.to.shared.u64 t, %1; cvt.u32.u64 %0, t; }" : "=r"(a) : "l"(p));
    return a;
}

// ---------------- kernel 1: normalize prototypes -> coalesced bf16 frags ----------------
__global__ void prep_kernel(const float* __restrict__ P) {
    int k = blockIdx.x;          // 64 blocks (one proto each)
    int t = threadIdx.x;         // 128 threads
    const float* row = P + k * PDIM;
    if (t == 0) g_Cnt[k] = 0;    // re-zeroed every replay before fused kernel

    float ss = 0.f;
    #pragma unroll
    for (int i = 0; i < 4; ++i) { float v = row[t + 128 * i]; ss += v * v; }
    __shared__ float red[4];
    #pragma unroll
    for (int o = 16; o > 0; o >>= 1) ss += __shfl_xor_sync(0xffffffffu, ss, o);
    if ((t & 31) == 0) red[t >> 5] = ss;
    __syncthreads();
    float norm = sqrtf(red[0] + red[1] + red[2] + red[3]);
    float inv = 1.f / fmaxf(norm, EPSN);

    int ks = t >> 2, q = t & 3;                    // 32 ksteps x 4 q
    int i0 = ks * 8 + q;                           // float2 index in row
    float2 fa = make_float2(row[2 * i0] * inv,       row[2 * i0 + 1] * inv);
    float2 fb = make_float2(row[2 * (i0 + 4)] * inv, row[2 * (i0 + 4) + 1] * inv);
    __nv_bfloat162 ha = __float22bfloat162_rn(fa);
    __nv_bfloat162 hb = __float22bfloat162_rn(fb);
    uint2 u;
    u.x = *reinterpret_cast<uint32_t*>(&ha);
    u.y = *reinterpret_cast<uint32_t*>(&hb);
    g_B[((k >> 3) * 32 + ks) * 32 + (k & 7) * 4 + q] = u;
}

// ---------------- kernel 2: FUSED, software-pipelined, float4 accumulator RMW ----------------
// 148 persistent CTAs x 512 threads, 2 __syncthreads per chunk.
// Per chunk k: stage(k)->buf[k&1]; S1; prefetch(k+1); {MMA(k) || accumulate(k-1)}
// in ONE phase (warps overlap tensor + smem pipes); S2; reduce cand -> s_asg[k&1].
// Accumulate: thread -> (row octet t>>7, float4 column t&127); 8x LDS.128/STS.128
// RMW (halved instr count + halved alias-serialized chain vs float2 version).
__global__ __launch_bounds__(512) void fused_kernel(const float* __restrict__ F) {
    extern __shared__ float acc[];                        // 64*512 f32 = 128 KB
    char*  s_A   = (char*)(acc + NPROTO * PDIM);          // 2 bufs x 32 rows x 1024B
    float* candV = (float*)(s_A + 2 * CHUNK * 1024);      // [8][32]
    int*   candI = (int*)(candV + 8 * 32);                // [8][32]
    unsigned char* s_asg = (unsigned char*)(candI + 8 * 32);  // [2][32], 8B-aligned

    int t = threadIdx.x;
    #pragma unroll
    for (int i = 0; i < NPROTO; ++i) acc[i * PDIM + t] = 0.f;

    int w = t >> 5, lane = t & 31;
    int pg = w & 7;                       // proto group (protos pg*8..pg*8+7)
    int rb = w >> 3;                      // row block (rows rb*16..rb*16+15)
    int q = lane & 3, rg = lane >> 2;
    int rowB = rb * 16 + (lane & 15);     // ldmatrix row
    int halfSel = lane >> 4;              // 16B half selector
    uint32_t sA0 = smem_u32(s_A);

    // resident B fragments: one proto group per warp (64 regs)
    uint2 Bf[32];
    #pragma unroll
    for (int ks = 0; ks < 32; ++ks) Bf[ks] = g_B[(pg * 32 + ks) * 32 + lane];

    // accumulate addressing: thread t -> row octet rh4, float4 column cp4
    int rh4 = t >> 7;                     // 0..3 -> rows rh4*8..rh4*8+7
    int cp4 = t & 127;                    // float4 column group (cols 4cp4..4cp4+3)
    int i16c = cp4 >> 1, inoffc = (cp4 & 1) * 8;
    float4* accp4 = reinterpret_cast<float4*>(acc);

    const float4* F4 = reinterpret_cast<const float4*>(F);
    int n = (NCHUNK - blockIdx.x + NACC - 1) / NACC;      // 42 or 43 chunks
    int cnt = 0;

    // prologue: prefetch + convert chunk 0 (8 x LDG.128 per thread, coalesced)
    uint2 u[8];
    {
        size_t cb = (size_t)blockIdx.x * (CHUNK * 128);
        #pragma unroll
        for (int j = 0; j < 8; ++j) {
            float4 v = F4[cb + j * 512 + t];
            __nv_bfloat162 h0 = __float22bfloat162_rn(make_float2(v.x, v.y));
            __nv_bfloat162 h1 = __float22bfloat162_rn(make_float2(v.z, v.w));
            u[j].x = *reinterpret_cast<uint32_t*>(&h0);
            u[j].y = *reinterpret_cast<uint32_t*>(&h1);
        }
    }
    __syncthreads();

    for (int k = 0; k < n; ++k) {
        // ---- stage chunk k into buf k&1 ----
        char* dst = s_A + (k & 1) * (CHUNK * 1024);
        #pragma unroll
        for (int j = 0; j < 8; ++j) {
            int idx = j * 512 + t;                // 0..4095 float4s
            int row = idx >> 7;                   // 128 float4 per row
            int c4  = idx & 127;
            int i16 = c4 >> 1;
            int sw  = (i16 & ~7) | ((i16 ^ row) & 7);
            *reinterpret_cast<uint2*>(dst + row * 1024 + sw * 16 + (c4 & 1) * 8) = u[j];
        }
        __syncthreads();   // S1: staging visible (also orders s_asg[k-1] reduce)

        // ---- prefetch + convert chunk k+1 ----
        if (k + 1 < n) {
            size_t cb = (size_t)(blockIdx.x + (k + 1) * NACC) * (CHUNK * 128);
            #pragma unroll
            for (int j = 0; j < 8; ++j) {
                float4 v = F4[cb + j * 512 + t];
                __nv_bfloat162 h0 = __float22bfloat162_rn(make_float2(v.x, v.y));
                __nv_bfloat162 h1 = __float22bfloat162_rn(make_float2(v.z, v.w));
                u[j].x = *reinterpret_cast<uint32_t*>(&h0);
                u[j].y = *reinterpret_cast<uint32_t*>(&h1);
            }
        }

        // ---- MMA on chunk k (this warp: 16 rows x 8 protos) ----
        {
            uint32_t base = sA0 + (uint32_t)(k & 1) * (CHUNK * 1024);
            float d0 = 0.f, d1 = 0.f, d2 = 0.f, d3 = 0.f;
            #pragma unroll
            for (int ks = 0; ks < 32; ++ks) {
                int i16 = ks * 2 + halfSel;
                int sw = (i16 & ~7) | ((i16 ^ rowB) & 7);
                uint32_t addr = base + rowB * 1024 + sw * 16;
                uint32_t a0, a1, a2, a3;
                asm volatile("ldmatrix.sync.aligned.m8n8.x4.shared.b16 {%0,%1,%2,%3}, [%4];"
                             : "=r"(a0), "=r"(a1), "=r"(a2), "=r"(a3) : "r"(addr));
                asm volatile(
                    "mma.sync.aligned.m16n8k16.row.col.f32.bf16.bf16.f32 "
                    "{%0,%1,%2,%3}, {%4,%5,%6,%7}, {%8,%9}, {%0,%1,%2,%3};"
                    : "+f"(d0), "+f"(d1), "+f"(d2), "+f"(d3)
                    : "r"(a0), "r"(a1), "r"(a2), "r"(a3), "r"(Bf[ks].x), "r"(Bf[ks].y));
            }
            // per-warp argmax over its 8 protos (lane holds cols 2q, 2q+1)
            #pragma unroll
            for (int half = 0; half < 2; ++half) {
                float e0 = half ? d2 : d0;
                float e1 = half ? d3 : d1;
                float bv = e0; int bi = pg * 8 + 2 * q;
                if (e1 > bv) { bv = e1; bi = pg * 8 + 2 * q + 1; }
                #pragma unroll
                for (int off = 1; off <= 2; off <<= 1) {
                    float ov = __shfl_xor_sync(0xffffffffu, bv, off);
                    int   oi = __shfl_xor_sync(0xffffffffu, bi, off);
                    if (ov > bv || (ov == bv && oi < bi)) { bv = ov; bi = oi; }
                }
                if (q == 0) {
                    int r32 = rb * 16 + half * 8 + rg;
                    candV[pg * 32 + r32] = bv;
                    candI[pg * 32 + r32] = bi;
                }
            }
        }

        // ---- accumulate chunk k-1 (same phase: overlaps MMA across warps) ----
        if (k > 0) {
            int pb = (k - 1) & 1;
            const char* src = s_A + pb * (CHUNK * 1024);
            unsigned long long w0 = *reinterpret_cast<const unsigned long long*>(s_asg + pb * 32 + rh4 * 8);
            #pragma unroll
            for (int j = 0; j < 8; ++j) {
                int r = rh4 * 8 + j;
                int sw = (i16c & ~7) | ((i16c ^ r) & 7);
                uint2 hv = *reinterpret_cast<const uint2*>(src + r * 1024 + sw * 16 + inoffc);
                __nv_bfloat162 h0 = *reinterpret_cast<__nv_bfloat162*>(&hv.x);
                __nv_bfloat162 h1 = *reinterpret_cast<__nv_bfloat162*>(&hv.y);
                float2 f0 = __bfloat1622float2(h0);
                float2 f1 = __bfloat1622float2(h1);
                int a = (int)((w0 >> (8 * j)) & 255ull);
                float4 cur = accp4[a * (PDIM / 4) + cp4];
                cur.x += f0.x; cur.y += f0.y; cur.z += f1.x; cur.w += f1.y;
                accp4[a * (PDIM / 4) + cp4] = cur;
            }
            if (t < NPROTO) {
                #pragma unroll
                for (int jj = 0; jj < 4; ++jj) {
                    unsigned long long x = *reinterpret_cast<const unsigned long long*>(s_asg + pb * 32 + jj * 8);
                    #pragma unroll
                    for (int b = 0; b < 8; ++b)
                        cnt += (int)(((x >> (8 * b)) & 255ull) == (unsigned long long)t);
                }
            }
        }
        __syncthreads();   // S2: cand complete; buf[(k-1)&1] free; s_asg[(k-1)&1] free

        // ---- reduce candidates -> s_asg[k&1] (ascending pg, strict >) ----
        if (t < CHUNK) {
            float bv = candV[t]; int bi = candI[t];
            #pragma unroll
            for (int g = 1; g < 8; ++g) {
                float ov = candV[g * 32 + t];
                if (ov > bv) { bv = ov; bi = candI[g * 32 + t]; }
            }
            s_asg[(k & 1) * 32 + t] = (unsigned char)bi;
        }
        // next iteration's S1 orders this write before its consumers
    }

    __syncthreads();
    // epilogue: accumulate last chunk n-1
    {
        int pb = (n - 1) & 1;
        const char* src = s_A + pb * (CHUNK * 1024);
        unsigned long long w0 = *reinterpret_cast<const unsigned long long*>(s_asg + pb * 32 + rh4 * 8);
        #pragma unroll
        for (int j = 0; j < 8; ++j) {
            int r = rh4 * 8 + j;
            int sw = (i16c & ~7) | ((i16c ^ r) & 7);
            uint2 hv = *reinterpret_cast<const uint2*>(src + r * 1024 + sw * 16 + inoffc);
            __nv_bfloat162 h0 = *reinterpret_cast<__nv_bfloat162*>(&hv.x);
            __nv_bfloat162 h1 = *reinterpret_cast<__nv_bfloat162*>(&hv.y);
            float2 f0 = __bfloat1622float2(h0);
            float2 f1 = __bfloat1622float2(h1);
            int a = (int)((w0 >> (8 * j)) & 255ull);
            float4 cur = accp4[a * (PDIM / 4) + cp4];
            cur.x += f0.x; cur.y += f0.y; cur.z += f1.x; cur.w += f1.y;
            accp4[a * (PDIM / 4) + cp4] = cur;
        }
        if (t < NPROTO) {
            #pragma unroll
            for (int jj = 0; jj < 4; ++jj) {
                unsigned long long x = *reinterpret_cast<const unsigned long long*>(s_asg + pb * 32 + jj * 8);
                #pragma unroll
                for (int b = 0; b < 8; ++b)
                    cnt += (int)(((x >> (8 * b)) & 255ull) == (unsigned long long)t);
            }
        }
    }
    __syncthreads();

    // deterministic flush of this CTA's partial slice
    float* part = g_Partial + (size_t)blockIdx.x * (NPROTO * PDIM);
    #pragma unroll 4
    for (int k = 0; k < NPROTO; ++k) part[k * PDIM + t] = acc[k * PDIM + t];
    if (t < NPROTO) atomicAdd(&g_Cnt[t], cnt);   // int atomics: deterministic
}

// ---------------- kernel 3: reduce partials + EMA update ----------------
__global__ void finalize_kernel(const float* __restrict__ P, float* __restrict__ out) {
    int k = blockIdx.x >> 3;                          // 64 protos x 8 col-groups
    int t = ((blockIdx.x & 7) << 6) + threadIdx.x;    // 64 threads -> column
    float s = 0.f;
    #pragma unroll 8
    for (int b = 0; b < NACC; ++b)
        s += g_Partial[(size_t)b * (NPROTO * PDIM) + k * PDIM + t];
    int c = g_Cnt[k];
    float p = P[k * PDIM + t];
    float mean = s / fmaxf((float)c, 1.f);
    out[k * PDIM + t] = (c > 0) ? (0.9f * p + 0.1f * mean) : p;
}

// ---------------- launch ----------------
extern "C" void kernel_launch(void* const* d_in, const int* in_sizes, int n_in,
                              void* d_out, int out_size) {
    const float* F = (const float*)d_in[0];
    const float* P = (const float*)d_in[1];
    if (in_sizes[0] == NPROTO * PDIM) {     // robust to input order
        F = (const float*)d_in[1];
        P = (const float*)d_in[0];
    }

    prep_kernel<<<NPROTO, 128>>>(P);

    int smem = NPROTO * PDIM * (int)sizeof(float)   // 128 KB accumulator
             + 2 * CHUNK * 1024                     // 64 KB double-buffered staging
             + 8 * 32 * (int)sizeof(float)          // candV
             + 8 * 32 * (int)sizeof(int)            // candI
             + 64;                                  // s_asg[2][32]
    cudaFuncSetAttribute(fused_kernel, cudaFuncAttributeMaxDynamicSharedMemorySize, smem);
    fused_kernel<<<NACC, 512, smem>>>(F);

    finalize_kernel<<<NPROTO * 8, 64>>>(P, (float*)d_out);
}